// round 2
// baseline (speedup 1.0000x reference)
#include <cuda_runtime.h>

#define BB   128
#define TT   512
#define HH   512
#define H3   1536
#define LATD 256
#define F2D  64
#define DIN  320
#define MT   65536   // B*T
#define NBLK 144     // persistent grid size (<= 148 SMs, all co-resident)

typedef unsigned long long ull;

// ---------------- device scratch (static, no allocation) ----------------
__device__ float g_AInT[(size_t)DIN * MT];       // [320][65536] transposed masked input
__device__ float g_X5[(size_t)MT * H3];          // [B*T][1536] x@W5 (no bias)
__device__ float g_g6T[(size_t)TT * HH * BB];    // [T][H][B] GRU6 hidden states
__device__ float g_h5T[HH * BB];                 // [H][B] current h5 (transposed)
__device__ float g_i5p[2][BB * H3];              // h5 @ U5 partial (ksplit)
__device__ float g_x6p[2][BB * H3];              // h5 @ W6 partial
__device__ float g_i6p[2][BB * H3];              // h6 @ U6 partial
__device__ float g_zeroA[HH * BB];               // zero A operand
__device__ unsigned g_bar_count;
__device__ unsigned g_bar_release;

// ---------------- packed f32x2 helpers ----------------
__device__ __forceinline__ void fma2(ull &acc, ull a, ull b) {
    asm("fma.rn.f32x2 %0, %1, %2, %0;" : "+l"(acc) : "l"(a), "l"(b));
}
__device__ __forceinline__ ull pack2(float x) {
    unsigned u = __float_as_uint(x);
    return ((ull)u << 32) | (ull)u;
}

// ---------------- grid barrier (persistent kernel) ----------------
__device__ __forceinline__ void grid_barrier(unsigned gen) {
    __syncthreads();
    if (threadIdx.x == 0) {
        __threadfence();
        if (atomicAdd(&g_bar_count, 1u) == NBLK - 1) {
            atomicExch(&g_bar_count, 0u);
            __threadfence();
            atomicExch(&g_bar_release, gen);
        } else {
            while ((int)(atomicAdd(&g_bar_release, 0u) - gen) < 0) { }
        }
        __threadfence();
    }
    __syncthreads();
}

// ---------------- GEMM tile: C[128 x 64] += A^T-stored @ B over k range ----
// AT: [K][lda] (A[m][k] at AT[k*lda+m]). B: [K][1536] row-major. C ldc=1536.
// 256 threads, per-thread 4m x 8n via f32x2.
__device__ __forceinline__ void gemm_body(
    const float* __restrict__ AT, int lda, int gm0,
    const float* __restrict__ Bm, int gn0,
    float* __restrict__ C, int k0beg, int k0end)
{
    __shared__ __align__(16) float As[16][128];
    __shared__ __align__(16) float Bs[16][64];
    const int tid = threadIdx.x;
    const int tx = tid & 7;    // 0..7  -> 8 n-columns (4 f32x2 pairs)
    const int ty = tid >> 3;   // 0..31 -> 4 m-rows

    ull acc[4][4];
#pragma unroll
    for (int i = 0; i < 4; i++)
#pragma unroll
        for (int j = 0; j < 4; j++) acc[i][j] = 0ULL;

    for (int k0 = k0beg; k0 < k0end; k0 += 16) {
        // A tile: 128x16 = 512 float4, 2 per thread (L2-coherent: cross-block data)
        {
            int v = tid;
#pragma unroll
            for (int it = 0; it < 2; it++, v += 256) {
                int kk = v >> 5, mm = (v & 31) << 2;
                float4 t4 = __ldcg((const float4*)&AT[(size_t)(k0 + kk) * lda + gm0 + mm]);
                *(float4*)&As[kk][mm] = t4;
            }
        }
        // B tile: 16x64 = 256 float4, 1 per thread (read-only weights, L1 ok)
        {
            int kk = tid >> 4, nn = (tid & 15) << 2;
            *(float4*)&Bs[kk][nn] = *(const float4*)&Bm[(size_t)(k0 + kk) * H3 + gn0 + nn];
        }
        __syncthreads();
#pragma unroll
        for (int kk = 0; kk < 16; kk++) {
            float4 av = *(const float4*)&As[kk][ty << 2];
            const ull* bp = (const ull*)&Bs[kk][tx << 3];
            ull b0 = bp[0], b1 = bp[1], b2 = bp[2], b3 = bp[3];
            ull a0 = pack2(av.x), a1 = pack2(av.y);
            ull a2 = pack2(av.z), a3 = pack2(av.w);
            fma2(acc[0][0], a0, b0); fma2(acc[0][1], a0, b1);
            fma2(acc[0][2], a0, b2); fma2(acc[0][3], a0, b3);
            fma2(acc[1][0], a1, b0); fma2(acc[1][1], a1, b1);
            fma2(acc[1][2], a1, b2); fma2(acc[1][3], a1, b3);
            fma2(acc[2][0], a2, b0); fma2(acc[2][1], a2, b1);
            fma2(acc[2][2], a2, b2); fma2(acc[2][3], a2, b3);
            fma2(acc[3][0], a3, b0); fma2(acc[3][1], a3, b1);
            fma2(acc[3][2], a3, b2); fma2(acc[3][3], a3, b3);
        }
        __syncthreads();
    }
#pragma unroll
    for (int i = 0; i < 4; i++) {
        float2 p0 = *(float2*)&acc[i][0];
        float2 p1 = *(float2*)&acc[i][1];
        float2 p2 = *(float2*)&acc[i][2];
        float2 p3 = *(float2*)&acc[i][3];
        int m = gm0 + (ty << 2) + i;
        float4 o0 = make_float4(p0.x, p0.y, p1.x, p1.y);
        float4 o1 = make_float4(p2.x, p2.y, p3.x, p3.y);
        *(float4*)&C[(size_t)m * H3 + gn0 + (tx << 3)]     = o0;
        *(float4*)&C[(size_t)m * H3 + gn0 + (tx << 3) + 4] = o1;
    }
}

// ---------------- small kernels ----------------
__global__ void k_zero() {
    int i = blockIdx.x * 256 + threadIdx.x;
    if (i < HH * BB) g_zeroA[i] = 0.0f;
    if (i == 0) { g_bar_count = 0u; g_bar_release = 0u; }
}

// build transposed masked input: AInT[k][m] = mask[m] * concat(z,x2)[m][k]
__global__ void k_build_aint(const float* __restrict__ z,
                             const float* __restrict__ x2,
                             const float* __restrict__ masks) {
    int idx = blockIdx.x * 256 + threadIdx.x;      // 320*65536 exact
    int k = idx >> 16, m = idx & 65535;
    int b = m >> 9;
    float v = (k < LATD) ? z[(b << 8) + k] : x2[(size_t)m * F2D + (k - LATD)];
    g_AInT[idx] = v * masks[m];
}

__global__ void k_gemm_x5(const float* __restrict__ W5) {
    gemm_body(g_AInT, MT, blockIdx.y * 128, W5, blockIdx.x * 64, g_X5, 0, DIN);
}

// ---------------- persistent recurrence kernel ----------------
__global__ void __launch_bounds__(256, 1)
k_recur(const float* __restrict__ U5, const float* __restrict__ W6,
        const float* __restrict__ U6,
        const float* __restrict__ bi5, const float* __restrict__ br5,
        const float* __restrict__ bi6, const float* __restrict__ br6)
{
    const int bid = blockIdx.x;
    unsigned gen = 0;

    for (int t = 0; t <= TT + 1; ++t) {
        // ---- gates phase: 2*65536 elements over 144 blocks ----
        for (int idx = bid * 256 + threadIdx.x; idx < 2 * 65536; idx += NBLK * 256) {
            int part = idx >> 16;
            int i = idx & 65535;
            int b = i >> 9, j = i & 511;
            if (part == 0) {
                if (t == 0) {
                    g_h5T[j * BB + b] = 0.0f;
                } else if (t <= TT) {
                    int tt = t - 1;
                    size_t xb = ((size_t)(b * TT + tt)) * H3 + j;
                    float xz = g_X5[xb]        + bi5[j];
                    float xr = g_X5[xb + 512]  + bi5[512 + j];
                    float xh = g_X5[xb + 1024] + bi5[1024 + j];
                    int ib = b * H3 + j;
                    float iz = __ldcg(&g_i5p[0][ib])        + __ldcg(&g_i5p[1][ib])        + br5[j];
                    float ir = __ldcg(&g_i5p[0][ib + 512])  + __ldcg(&g_i5p[1][ib + 512])  + br5[512 + j];
                    float ih = __ldcg(&g_i5p[0][ib + 1024]) + __ldcg(&g_i5p[1][ib + 1024]) + br5[1024 + j];
                    float zg = __saturatef(0.2f * (xz + iz) + 0.5f);
                    float rg = __saturatef(0.2f * (xr + ir) + 0.5f);
                    float hh = tanhf(xh + rg * ih);
                    float hold = __ldcg(&g_h5T[j * BB + b]);
                    g_h5T[j * BB + b] = zg * hold + (1.0f - zg) * hh;
                }
            } else {
                if (t >= 2) {
                    int tt = t - 2;
                    int ib = b * H3 + j;
                    float xz = __ldcg(&g_x6p[0][ib])        + __ldcg(&g_x6p[1][ib])        + bi6[j];
                    float xr = __ldcg(&g_x6p[0][ib + 512])  + __ldcg(&g_x6p[1][ib + 512])  + bi6[512 + j];
                    float xh = __ldcg(&g_x6p[0][ib + 1024]) + __ldcg(&g_x6p[1][ib + 1024]) + bi6[1024 + j];
                    float iz = __ldcg(&g_i6p[0][ib])        + __ldcg(&g_i6p[1][ib])        + br6[j];
                    float ir = __ldcg(&g_i6p[0][ib + 512])  + __ldcg(&g_i6p[1][ib + 512])  + br6[512 + j];
                    float ih = __ldcg(&g_i6p[0][ib + 1024]) + __ldcg(&g_i6p[1][ib + 1024]) + br6[1024 + j];
                    float zg = __saturatef(0.2f * (xz + iz) + 0.5f);
                    float rg = __saturatef(0.2f * (xr + ir) + 0.5f);
                    float hh = tanhf(xh + rg * ih);
                    float hold = (tt >= 1) ? __ldcg(&g_g6T[(size_t)(tt - 1) * HH * BB + j * BB + b]) : 0.0f;
                    g_g6T[(size_t)tt * HH * BB + j * BB + b] = zg * hold + (1.0f - zg) * hh;
                }
            }
        }
        grid_barrier(++gen);

        // ---- gemm phase: 3 matrices x 24 n-tiles x 2 k-halves = 144 blocks ----
        if (t <= TT) {
            int g = bid / 48, r = bid % 48;
            int nt = r >> 1, part = r & 1;
            const float* AT; const float* Bm; float* C;
            if (g == 0)      { AT = g_h5T; Bm = U5; C = g_i5p[part]; }
            else if (g == 1) { AT = g_h5T; Bm = W6; C = g_x6p[part]; }
            else {
                AT = (t >= 2) ? (g_g6T + (size_t)(t - 2) * HH * BB) : g_zeroA;
                Bm = U6; C = g_i6p[part];
            }
            gemm_body(AT, BB, 0, Bm, nt * 64, C, part * 256, part * 256 + 256);
        }
        grid_barrier(++gen);
    }
}

// out[b][t] = tanh(g6[b,t,:] . Wd + bd) * dec_mask
__global__ void k_dense(const float* __restrict__ Wd, const float* __restrict__ bd,
                        const float* __restrict__ dmask, float* __restrict__ out) {
    __shared__ float wd[HH];
    int t = blockIdx.x, b = threadIdx.x;  // 128 threads
    for (int j = b; j < HH; j += 128) wd[j] = Wd[j];
    __syncthreads();
    const float* src = g_g6T + (size_t)t * HH * BB + b;
    float acc = 0.0f;
#pragma unroll 8
    for (int j = 0; j < HH; j++) acc += src[(size_t)j * BB] * wd[j];
    out[b * TT + t] = tanhf(acc + bd[0]) * dmask[b * TT + t];
}

// ---------------- launch ----------------
extern "C" void kernel_launch(void* const* d_in, const int* in_sizes, int n_in,
                              void* d_out, int out_size) {
    const float* z   = (const float*)d_in[0];
    const float* x2  = (const float*)d_in[1];
    const float* mk  = (const float*)d_in[2];
    const float* dmk = (const float*)d_in[3];
    const float* W5  = (const float*)d_in[4];
    const float* U5  = (const float*)d_in[5];
    const float* bi5 = (const float*)d_in[6];
    const float* br5 = (const float*)d_in[7];
    const float* W6  = (const float*)d_in[8];
    const float* U6  = (const float*)d_in[9];
    const float* bi6 = (const float*)d_in[10];
    const float* br6 = (const float*)d_in[11];
    const float* Wd  = (const float*)d_in[12];
    const float* bd  = (const float*)d_in[13];
    float* out = (float*)d_out;

    k_zero<<<256, 256>>>();
    k_build_aint<<<81920, 256>>>(z, x2, mk);
    k_gemm_x5<<<dim3(24, 512), 256>>>(W5);
    k_recur<<<NBLK, 256>>>(U5, W6, U6, bi5, br5, bi6, br6);
    k_dense<<<TT, 128>>>(Wd, bd, dmk, out);
}

// round 3
// speedup vs baseline: 1.0832x; 1.0832x over previous
#include <cuda_runtime.h>

#define BB   128
#define TT   512
#define HH   512
#define H3   1536
#define LATD 256
#define F2D  64
#define DIN  320
#define MT   65536   // B*T
#define NBLK 144     // persistent grid size (<= 148 SMs, all co-resident)

typedef unsigned long long ull;

// ---------------- device scratch (static, no allocation) ----------------
__device__ float g_AInT[(size_t)DIN * MT];       // [320][65536] transposed masked input
__device__ float g_X5[(size_t)MT * H3];          // [B*T][1536] x@W5 (no bias)
__device__ float g_g6T[(size_t)TT * HH * BB];    // [T][H][B] GRU6 hidden states
__device__ float g_h5T[HH * BB];                 // [H][B] current h5 (transposed)
__device__ float g_i5p[2][BB * H3];              // h5 @ U5 partial (ksplit)
__device__ float g_x6p[2][BB * H3];              // h5 @ W6 partial
__device__ float g_i6p[2][BB * H3];              // h6 @ U6 partial
__device__ float g_zeroA[HH * BB];               // zero A operand
__device__ unsigned g_bar_count;
__device__ unsigned g_bar_release;

// ---------------- helpers ----------------
__device__ __forceinline__ void fma2(ull &acc, ull a, ull b) {
    asm("fma.rn.f32x2 %0, %1, %2, %0;" : "+l"(acc) : "l"(a), "l"(b));
}
__device__ __forceinline__ ull pack2(float x) {
    ull r;
    asm("mov.b64 %0, {%1, %1};" : "=l"(r) : "r"(__float_as_uint(x)));
    return r;
}
__device__ __forceinline__ float fast_tanh(float x) {
    float y;
    asm("tanh.approx.f32 %0, %1;" : "=f"(y) : "f"(x));
    return y;
}

// ---------------- grid barrier (persistent kernel) ----------------
__device__ __forceinline__ void grid_barrier(unsigned gen) {
    __syncthreads();
    if (threadIdx.x == 0) {
        __threadfence();
        if (atomicAdd(&g_bar_count, 1u) == NBLK - 1) {
            g_bar_count = 0u;
            __threadfence();
            atomicExch(&g_bar_release, gen);
        } else {
            volatile unsigned* r = &g_bar_release;
            while ((int)(*r - gen) < 0) { }
        }
        __threadfence();
    }
    __syncthreads();
}

// ---------------- GEMM tile: C[128 x 64] = A^T-stored @ B over k range ----
// AT: [K][lda] (A[m][k] at AT[k*lda+m]). B: [K][1536] row-major. C ldc=1536.
// 256 threads, per-thread 4m x 8n via f32x2. A duplicated into (v,v) ull pairs
// in smem at fill time; double-buffered; one syncthreads per k0.
__device__ __forceinline__ void gemm_body(
    const float* __restrict__ AT, int lda, int gm0,
    const float* __restrict__ Bm, int gn0,
    float* __restrict__ C, int k0beg, int k0end)
{
    __shared__ __align__(16) ull   As[2][16][128];   // 32KB, duplicated pairs
    __shared__ __align__(16) float Bs[2][16][64];    // 8KB
    const int tid = threadIdx.x;
    const int tx = tid & 7;    // 0..7  -> 8 n-columns (4 f32x2 pairs)
    const int ty = tid >> 3;   // 0..31 -> 4 m-rows

    const int akk = tid >> 5;          // 0..7 (and +8 for second half)
    const int amm = (tid & 31) << 2;   // 0..124
    const int bkk = tid >> 4;          // 0..15
    const int bnn = (tid & 15) << 2;   // 0..60

    float4 ra0, ra1, rb;

    // prologue load
    ra0 = __ldcg((const float4*)&AT[(size_t)(k0beg + akk) * lda + gm0 + amm]);
    ra1 = __ldcg((const float4*)&AT[(size_t)(k0beg + akk + 8) * lda + gm0 + amm]);
    rb  = *(const float4*)&Bm[(size_t)(k0beg + bkk) * H3 + gn0 + bnn];
    {
        ulonglong2 d0; d0.x = pack2(ra0.x); d0.y = pack2(ra0.y);
        ulonglong2 d1; d1.x = pack2(ra0.z); d1.y = pack2(ra0.w);
        *(ulonglong2*)&As[0][akk][amm]     = d0;
        *(ulonglong2*)&As[0][akk][amm + 2] = d1;
        ulonglong2 d2; d2.x = pack2(ra1.x); d2.y = pack2(ra1.y);
        ulonglong2 d3; d3.x = pack2(ra1.z); d3.y = pack2(ra1.w);
        *(ulonglong2*)&As[0][akk + 8][amm]     = d2;
        *(ulonglong2*)&As[0][akk + 8][amm + 2] = d3;
        *(float4*)&Bs[0][bkk][bnn] = rb;
    }
    __syncthreads();

    ull acc[4][4];
#pragma unroll
    for (int i = 0; i < 4; i++)
#pragma unroll
        for (int j = 0; j < 4; j++) acc[i][j] = 0ULL;

    int p = 0;
    for (int k0 = k0beg; k0 < k0end; k0 += 16) {
        const bool has_next = (k0 + 16) < k0end;
        if (has_next) {
            ra0 = __ldcg((const float4*)&AT[(size_t)(k0 + 16 + akk) * lda + gm0 + amm]);
            ra1 = __ldcg((const float4*)&AT[(size_t)(k0 + 16 + akk + 8) * lda + gm0 + amm]);
            rb  = *(const float4*)&Bm[(size_t)(k0 + 16 + bkk) * H3 + gn0 + bnn];
        }
#pragma unroll
        for (int kk = 0; kk < 16; kk++) {
            ulonglong2 a01 = *(const ulonglong2*)&As[p][kk][ty << 2];
            ulonglong2 a23 = *(const ulonglong2*)&As[p][kk][(ty << 2) + 2];
            ulonglong2 bA  = *(const ulonglong2*)&Bs[p][kk][tx << 3];
            ulonglong2 bB  = *(const ulonglong2*)&Bs[p][kk][(tx << 3) + 4];
            fma2(acc[0][0], a01.x, bA.x); fma2(acc[0][1], a01.x, bA.y);
            fma2(acc[0][2], a01.x, bB.x); fma2(acc[0][3], a01.x, bB.y);
            fma2(acc[1][0], a01.y, bA.x); fma2(acc[1][1], a01.y, bA.y);
            fma2(acc[1][2], a01.y, bB.x); fma2(acc[1][3], a01.y, bB.y);
            fma2(acc[2][0], a23.x, bA.x); fma2(acc[2][1], a23.x, bA.y);
            fma2(acc[2][2], a23.x, bB.x); fma2(acc[2][3], a23.x, bB.y);
            fma2(acc[3][0], a23.y, bA.x); fma2(acc[3][1], a23.y, bA.y);
            fma2(acc[3][2], a23.y, bB.x); fma2(acc[3][3], a23.y, bB.y);
        }
        if (has_next) {
            const int q = p ^ 1;
            ulonglong2 d0; d0.x = pack2(ra0.x); d0.y = pack2(ra0.y);
            ulonglong2 d1; d1.x = pack2(ra0.z); d1.y = pack2(ra0.w);
            *(ulonglong2*)&As[q][akk][amm]     = d0;
            *(ulonglong2*)&As[q][akk][amm + 2] = d1;
            ulonglong2 d2; d2.x = pack2(ra1.x); d2.y = pack2(ra1.y);
            ulonglong2 d3; d3.x = pack2(ra1.z); d3.y = pack2(ra1.w);
            *(ulonglong2*)&As[q][akk + 8][amm]     = d2;
            *(ulonglong2*)&As[q][akk + 8][amm + 2] = d3;
            *(float4*)&Bs[q][bkk][bnn] = rb;
        }
        __syncthreads();
        p ^= 1;
    }

#pragma unroll
    for (int i = 0; i < 4; i++) {
        float2 p0 = *(float2*)&acc[i][0];
        float2 p1 = *(float2*)&acc[i][1];
        float2 p2 = *(float2*)&acc[i][2];
        float2 p3 = *(float2*)&acc[i][3];
        int m = gm0 + (ty << 2) + i;
        float4 o0 = make_float4(p0.x, p0.y, p1.x, p1.y);
        float4 o1 = make_float4(p2.x, p2.y, p3.x, p3.y);
        *(float4*)&C[(size_t)m * H3 + gn0 + (tx << 3)]     = o0;
        *(float4*)&C[(size_t)m * H3 + gn0 + (tx << 3) + 4] = o1;
    }
}

// ---------------- small kernels ----------------
__global__ void k_zero() {
    int i = blockIdx.x * 256 + threadIdx.x;
    if (i < HH * BB) g_zeroA[i] = 0.0f;
    if (i == 0) { g_bar_count = 0u; g_bar_release = 0u; }
}

// build transposed masked input: AInT[k][m] = mask[m] * concat(z,x2)[m][k]
__global__ void k_build_aint(const float* __restrict__ z,
                             const float* __restrict__ x2,
                             const float* __restrict__ masks) {
    int idx = blockIdx.x * 256 + threadIdx.x;      // 320*65536 exact
    int k = idx >> 16, m = idx & 65535;
    int b = m >> 9;
    float v = (k < LATD) ? z[(b << 8) + k] : x2[(size_t)m * F2D + (k - LATD)];
    g_AInT[idx] = v * masks[m];
}

__global__ void __launch_bounds__(256) k_gemm_x5(const float* __restrict__ W5) {
    gemm_body(g_AInT, MT, blockIdx.y * 128, W5, blockIdx.x * 64, g_X5, 0, DIN);
}

// ---------------- persistent recurrence kernel ----------------
__global__ void __launch_bounds__(256, 1)
k_recur(const float* __restrict__ U5, const float* __restrict__ W6,
        const float* __restrict__ U6,
        const float* __restrict__ bi5, const float* __restrict__ br5,
        const float* __restrict__ bi6, const float* __restrict__ br6)
{
    const int bid = blockIdx.x;
    unsigned gen = 0;

    for (int t = 0; t <= TT + 1; ++t) {
        // ---- gates phase: 2*65536 elements over 144 blocks ----
        for (int idx = bid * 256 + threadIdx.x; idx < 2 * 65536; idx += NBLK * 256) {
            int part = idx >> 16;
            int i = idx & 65535;
            int b = i >> 9, j = i & 511;
            if (part == 0) {
                if (t == 0) {
                    g_h5T[j * BB + b] = 0.0f;
                } else if (t <= TT) {
                    int tt = t - 1;
                    size_t xb = ((size_t)(b * TT + tt)) * H3 + j;
                    float xz = g_X5[xb]        + bi5[j];
                    float xr = g_X5[xb + 512]  + bi5[512 + j];
                    float xh = g_X5[xb + 1024] + bi5[1024 + j];
                    int ib = b * H3 + j;
                    float iz = __ldcg(&g_i5p[0][ib])        + __ldcg(&g_i5p[1][ib])        + br5[j];
                    float ir = __ldcg(&g_i5p[0][ib + 512])  + __ldcg(&g_i5p[1][ib + 512])  + br5[512 + j];
                    float ih = __ldcg(&g_i5p[0][ib + 1024]) + __ldcg(&g_i5p[1][ib + 1024]) + br5[1024 + j];
                    float zg = __saturatef(0.2f * (xz + iz) + 0.5f);
                    float rg = __saturatef(0.2f * (xr + ir) + 0.5f);
                    float hh = fast_tanh(xh + rg * ih);
                    float hold = __ldcg(&g_h5T[j * BB + b]);
                    g_h5T[j * BB + b] = zg * hold + (1.0f - zg) * hh;
                }
            } else {
                if (t >= 2) {
                    int tt = t - 2;
                    int ib = b * H3 + j;
                    float xz = __ldcg(&g_x6p[0][ib])        + __ldcg(&g_x6p[1][ib])        + bi6[j];
                    float xr = __ldcg(&g_x6p[0][ib + 512])  + __ldcg(&g_x6p[1][ib + 512])  + bi6[512 + j];
                    float xh = __ldcg(&g_x6p[0][ib + 1024]) + __ldcg(&g_x6p[1][ib + 1024]) + bi6[1024 + j];
                    float iz = __ldcg(&g_i6p[0][ib])        + __ldcg(&g_i6p[1][ib])        + br6[j];
                    float ir = __ldcg(&g_i6p[0][ib + 512])  + __ldcg(&g_i6p[1][ib + 512])  + br6[512 + j];
                    float ih = __ldcg(&g_i6p[0][ib + 1024]) + __ldcg(&g_i6p[1][ib + 1024]) + br6[1024 + j];
                    float zg = __saturatef(0.2f * (xz + iz) + 0.5f);
                    float rg = __saturatef(0.2f * (xr + ir) + 0.5f);
                    float hh = fast_tanh(xh + rg * ih);
                    float hold = (tt >= 1) ? __ldcg(&g_g6T[(size_t)(tt - 1) * HH * BB + j * BB + b]) : 0.0f;
                    g_g6T[(size_t)tt * HH * BB + j * BB + b] = zg * hold + (1.0f - zg) * hh;
                }
            }
        }
        grid_barrier(++gen);

        // ---- gemm phase: 3 matrices x 12 n-tiles x 2 k-halves ... 144 blocks ----
        if (t <= TT) {
            int g = bid / 48, r = bid % 48;
            int nt = r >> 1, part = r & 1;
            const float* AT; const float* Bm; float* C;
            if (g == 0)      { AT = g_h5T; Bm = U5; C = g_i5p[part]; }
            else if (g == 1) { AT = g_h5T; Bm = W6; C = g_x6p[part]; }
            else {
                AT = (t >= 2) ? (g_g6T + (size_t)(t - 2) * HH * BB) : g_zeroA;
                Bm = U6; C = g_i6p[part];
            }
            gemm_body(AT, BB, 0, Bm, nt * 64, C, part * 256, part * 256 + 256);
        }
        grid_barrier(++gen);
    }
}

// out[b][t] = tanh(g6[b,t,:] . Wd + bd) * dec_mask
__global__ void k_dense(const float* __restrict__ Wd, const float* __restrict__ bd,
                        const float* __restrict__ dmask, float* __restrict__ out) {
    __shared__ float wd[HH];
    int t = blockIdx.x, b = threadIdx.x;  // 128 threads
    for (int j = b; j < HH; j += 128) wd[j] = Wd[j];
    __syncthreads();
    const float* src = g_g6T + (size_t)t * HH * BB + b;
    float acc = 0.0f;
#pragma unroll 8
    for (int j = 0; j < HH; j++) acc += src[(size_t)j * BB] * wd[j];
    out[b * TT + t] = fast_tanh(acc + bd[0]) * dmask[b * TT + t];
}

// ---------------- launch ----------------
extern "C" void kernel_launch(void* const* d_in, const int* in_sizes, int n_in,
                              void* d_out, int out_size) {
    const float* z   = (const float*)d_in[0];
    const float* x2  = (const float*)d_in[1];
    const float* mk  = (const float*)d_in[2];
    const float* dmk = (const float*)d_in[3];
    const float* W5  = (const float*)d_in[4];
    const float* U5  = (const float*)d_in[5];
    const float* bi5 = (const float*)d_in[6];
    const float* br5 = (const float*)d_in[7];
    const float* W6  = (const float*)d_in[8];
    const float* U6  = (const float*)d_in[9];
    const float* bi6 = (const float*)d_in[10];
    const float* br6 = (const float*)d_in[11];
    const float* Wd  = (const float*)d_in[12];
    const float* bd  = (const float*)d_in[13];
    float* out = (float*)d_out;

    k_zero<<<256, 256>>>();
    k_build_aint<<<81920, 256>>>(z, x2, mk);
    k_gemm_x5<<<dim3(24, 512), 256>>>(W5);
    k_recur<<<NBLK, 256>>>(U5, W6, U6, bi5, br5, bi6, br6);
    k_dense<<<TT, 128>>>(Wd, bd, dmk, out);
}

// round 5
// speedup vs baseline: 1.3204x; 1.2189x over previous
#include <cuda_runtime.h>

#define BB   128
#define TT   512
#define HH   512
#define H3   1536
#define LATD 256
#define F2D  64
#define DIN  320
#define MT   65536   // B*T
#define NBLK 144     // persistent grid size (<= 148 SMs, all co-resident)
#define KSP  4       // k-split for step gemms

typedef unsigned long long ull;

// ---------------- device scratch (static, no allocation) ----------------
__device__ float g_AInT[(size_t)DIN * MT];       // [320][65536] transposed masked input
__device__ float g_X5[(size_t)MT * H3];          // [B*T][1536] x@W5 (no bias)
__device__ float g_g6T[(size_t)TT * HH * BB];    // [T][H][B] GRU6 hidden states
__device__ float g_h5T[HH * BB];                 // [H][B] current h5 (transposed)
__device__ float g_i5p[KSP][BB * H3];            // h5 @ U5 partials
__device__ float g_x6p[KSP][BB * H3];            // h5 @ W6 partials
__device__ float g_i6p[KSP][BB * H3];            // h6 @ U6 partials
__device__ float g_zeroA[HH * BB];               // zero A operand
__device__ unsigned g_bar_count;
__device__ unsigned g_bar_release;

// ---------------- helpers ----------------
__device__ __forceinline__ void fma2(ull &acc, ull a, ull b) {
    asm("fma.rn.f32x2 %0, %1, %2, %0;" : "+l"(acc) : "l"(a), "l"(b));
}
__device__ __forceinline__ ull pack2(float x) {
    ull r;
    asm("mov.b64 %0, {%1, %1};" : "=l"(r) : "r"(__float_as_uint(x)));
    return r;
}
__device__ __forceinline__ float fast_tanh(float x) {
    float y;
    asm("tanh.approx.f32 %0, %1;" : "=f"(y) : "f"(x));
    return y;
}

// ---------------- grid barrier (persistent kernel) ----------------
__device__ __forceinline__ void grid_barrier(unsigned gen) {
    __syncthreads();
    if (threadIdx.x == 0) {
        __threadfence();
        if (atomicAdd(&g_bar_count, 1u) == NBLK - 1) {
            g_bar_count = 0u;
            __threadfence();
            atomicExch(&g_bar_release, gen);
        } else {
            volatile unsigned* r = &g_bar_release;
            while ((int)(*r - gen) < 0) { }
        }
        __threadfence();
    }
    __syncthreads();
}

// ---------------- GEMM tile: C[128 x 128] = A^T-stored @ B over k range ----
// AT: [K][lda] (A[m][k] at AT[k*lda+m]). B: [K][1536] row-major. C ldc=1536.
// 256 threads, per-thread 8m x 8n via f32x2. A pre-duplicated as (v,v) ull in
// smem; double-buffered; broadcast-friendly thread map (tx=n-group, ty=m-group).
__device__ __forceinline__ void gemm_body(
    const float* __restrict__ AT, int lda, int gm0,
    const float* __restrict__ Bm, int gn0,
    float* __restrict__ C, int k0beg, int k0end)
{
    __shared__ __align__(16) ull   As[2][16][128];   // duplicated pairs, 16KBx2
    __shared__ __align__(16) float Bs[2][16][128];   // 8KBx2
    const int tid = threadIdx.x;
    const int tx = tid & 15;           // n-group: 8 floats (4 f32x2)
    const int ty = tid >> 4;           // m-group: 8 rows (8 dup ull)

    const int akk = tid >> 5;          // 0..7 (+8 second half)
    const int amm = (tid & 31) << 2;   // 0..124
    const int bkk = tid >> 4;          // 0..15
    const int bnn = (tid & 15) << 3;   // 0..120

    float4 ra0, ra1, rb0, rb1;

    // prologue load + fill buffer 0
    ra0 = __ldcg((const float4*)&AT[(size_t)(k0beg + akk) * lda + gm0 + amm]);
    ra1 = __ldcg((const float4*)&AT[(size_t)(k0beg + akk + 8) * lda + gm0 + amm]);
    rb0 = *(const float4*)&Bm[(size_t)(k0beg + bkk) * H3 + gn0 + bnn];
    rb1 = *(const float4*)&Bm[(size_t)(k0beg + bkk) * H3 + gn0 + bnn + 4];
    {
        ulonglong2 d;
        d.x = pack2(ra0.x); d.y = pack2(ra0.y); *(ulonglong2*)&As[0][akk][amm]     = d;
        d.x = pack2(ra0.z); d.y = pack2(ra0.w); *(ulonglong2*)&As[0][akk][amm + 2] = d;
        d.x = pack2(ra1.x); d.y = pack2(ra1.y); *(ulonglong2*)&As[0][akk + 8][amm]     = d;
        d.x = pack2(ra1.z); d.y = pack2(ra1.w); *(ulonglong2*)&As[0][akk + 8][amm + 2] = d;
        *(float4*)&Bs[0][bkk][bnn]     = rb0;
        *(float4*)&Bs[0][bkk][bnn + 4] = rb1;
    }
    __syncthreads();

    ull acc[8][4];
#pragma unroll
    for (int i = 0; i < 8; i++)
#pragma unroll
        for (int j = 0; j < 4; j++) acc[i][j] = 0ULL;

    int p = 0;
    for (int k0 = k0beg; k0 < k0end; k0 += 16) {
        const bool has_next = (k0 + 16) < k0end;
        if (has_next) {
            ra0 = __ldcg((const float4*)&AT[(size_t)(k0 + 16 + akk) * lda + gm0 + amm]);
            ra1 = __ldcg((const float4*)&AT[(size_t)(k0 + 16 + akk + 8) * lda + gm0 + amm]);
            rb0 = *(const float4*)&Bm[(size_t)(k0 + 16 + bkk) * H3 + gn0 + bnn];
            rb1 = *(const float4*)&Bm[(size_t)(k0 + 16 + bkk) * H3 + gn0 + bnn + 4];
        }
#pragma unroll
        for (int kk = 0; kk < 16; kk++) {
            const ull* ap = &As[p][kk][ty << 3];
            ulonglong2 a01 = *(const ulonglong2*)(ap);
            ulonglong2 a23 = *(const ulonglong2*)(ap + 2);
            ulonglong2 a45 = *(const ulonglong2*)(ap + 4);
            ulonglong2 a67 = *(const ulonglong2*)(ap + 6);
            const ull* bp = (const ull*)&Bs[p][kk][tx << 3];
            ulonglong2 bq0 = *(const ulonglong2*)(bp);
            ulonglong2 bq1 = *(const ulonglong2*)(bp + 2);
            fma2(acc[0][0], a01.x, bq0.x); fma2(acc[0][1], a01.x, bq0.y);
            fma2(acc[0][2], a01.x, bq1.x); fma2(acc[0][3], a01.x, bq1.y);
            fma2(acc[1][0], a01.y, bq0.x); fma2(acc[1][1], a01.y, bq0.y);
            fma2(acc[1][2], a01.y, bq1.x); fma2(acc[1][3], a01.y, bq1.y);
            fma2(acc[2][0], a23.x, bq0.x); fma2(acc[2][1], a23.x, bq0.y);
            fma2(acc[2][2], a23.x, bq1.x); fma2(acc[2][3], a23.x, bq1.y);
            fma2(acc[3][0], a23.y, bq0.x); fma2(acc[3][1], a23.y, bq0.y);
            fma2(acc[3][2], a23.y, bq1.x); fma2(acc[3][3], a23.y, bq1.y);
            fma2(acc[4][0], a45.x, bq0.x); fma2(acc[4][1], a45.x, bq0.y);
            fma2(acc[4][2], a45.x, bq1.x); fma2(acc[4][3], a45.x, bq1.y);
            fma2(acc[5][0], a45.y, bq0.x); fma2(acc[5][1], a45.y, bq0.y);
            fma2(acc[5][2], a45.y, bq1.x); fma2(acc[5][3], a45.y, bq1.y);
            fma2(acc[6][0], a67.x, bq0.x); fma2(acc[6][1], a67.x, bq0.y);
            fma2(acc[6][2], a67.x, bq1.x); fma2(acc[6][3], a67.x, bq1.y);
            fma2(acc[7][0], a67.y, bq0.x); fma2(acc[7][1], a67.y, bq0.y);
            fma2(acc[7][2], a67.y, bq1.x); fma2(acc[7][3], a67.y, bq1.y);
        }
        if (has_next) {
            const int q = p ^ 1;
            ulonglong2 d;
            d.x = pack2(ra0.x); d.y = pack2(ra0.y); *(ulonglong2*)&As[q][akk][amm]     = d;
            d.x = pack2(ra0.z); d.y = pack2(ra0.w); *(ulonglong2*)&As[q][akk][amm + 2] = d;
            d.x = pack2(ra1.x); d.y = pack2(ra1.y); *(ulonglong2*)&As[q][akk + 8][amm]     = d;
            d.x = pack2(ra1.z); d.y = pack2(ra1.w); *(ulonglong2*)&As[q][akk + 8][amm + 2] = d;
            *(float4*)&Bs[q][bkk][bnn]     = rb0;
            *(float4*)&Bs[q][bkk][bnn + 4] = rb1;
        }
        __syncthreads();
        p ^= 1;
    }

#pragma unroll
    for (int i = 0; i < 8; i++) {
        float2 p0 = *(float2*)&acc[i][0];
        float2 p1 = *(float2*)&acc[i][1];
        float2 p2 = *(float2*)&acc[i][2];
        float2 p3 = *(float2*)&acc[i][3];
        int m = gm0 + (ty << 3) + i;
        *(float4*)&C[(size_t)m * H3 + gn0 + (tx << 3)]     = make_float4(p0.x, p0.y, p1.x, p1.y);
        *(float4*)&C[(size_t)m * H3 + gn0 + (tx << 3) + 4] = make_float4(p2.x, p2.y, p3.x, p3.y);
    }
}

// ---------------- small kernels ----------------
__global__ void k_zero() {
    int i = blockIdx.x * 256 + threadIdx.x;
    if (i < HH * BB) g_zeroA[i] = 0.0f;
    if (i == 0) { g_bar_count = 0u; g_bar_release = 0u; }
}

// build transposed masked input: AInT[k][m] = mask[m] * concat(z,x2)[m][k]
__global__ void k_build_aint(const float* __restrict__ z,
                             const float* __restrict__ x2,
                             const float* __restrict__ masks) {
    int idx = blockIdx.x * 256 + threadIdx.x;      // 320*65536 exact
    int k = idx >> 16, m = idx & 65535;
    int b = m >> 9;
    float v = (k < LATD) ? z[(b << 8) + k] : x2[(size_t)m * F2D + (k - LATD)];
    g_AInT[idx] = v * masks[m];
}

__global__ void __launch_bounds__(256) k_gemm_x5(const float* __restrict__ W5) {
    gemm_body(g_AInT, MT, blockIdx.y * 128, W5, blockIdx.x * 128, g_X5, 0, DIN);
}

// ---------------- persistent recurrence kernel ----------------
__global__ void __launch_bounds__(256, 1)
k_recur(const float* __restrict__ U5, const float* __restrict__ W6,
        const float* __restrict__ U6,
        const float* __restrict__ bi5, const float* __restrict__ br5,
        const float* __restrict__ bi6, const float* __restrict__ br6)
{
    const int bid = blockIdx.x;
    unsigned gen = 0;

    for (int t = 0; t <= TT + 1; ++t) {
        // ---- gates phase: 2*65536 elements over 144 blocks ----
        for (int idx = bid * 256 + threadIdx.x; idx < 2 * 65536; idx += NBLK * 256) {
            int part = idx >> 16;
            int i = idx & 65535;
            int b = i >> 9, j = i & 511;
            if (part == 0) {
                if (t == 0) {
                    g_h5T[j * BB + b] = 0.0f;
                } else if (t <= TT) {
                    int tt = t - 1;
                    size_t xb = ((size_t)(b * TT + tt)) * H3 + j;
                    float xz = g_X5[xb]        + bi5[j];
                    float xr = g_X5[xb + 512]  + bi5[512 + j];
                    float xh = g_X5[xb + 1024] + bi5[1024 + j];
                    int ib = b * H3 + j;
                    float iz = br5[j], ir = br5[512 + j], ih = br5[1024 + j];
#pragma unroll
                    for (int pp = 0; pp < KSP; pp++) {
                        iz += __ldcg(&g_i5p[pp][ib]);
                        ir += __ldcg(&g_i5p[pp][ib + 512]);
                        ih += __ldcg(&g_i5p[pp][ib + 1024]);
                    }
                    float zg = __saturatef(0.2f * (xz + iz) + 0.5f);
                    float rg = __saturatef(0.2f * (xr + ir) + 0.5f);
                    float hh = fast_tanh(xh + rg * ih);
                    float hold = __ldcg(&g_h5T[j * BB + b]);
                    g_h5T[j * BB + b] = zg * hold + (1.0f - zg) * hh;
                }
            } else {
                if (t >= 2) {
                    int tt = t - 2;
                    int ib = b * H3 + j;
                    float xz = bi6[j], xr = bi6[512 + j], xh = bi6[1024 + j];
                    float iz = br6[j], ir = br6[512 + j], ih = br6[1024 + j];
#pragma unroll
                    for (int pp = 0; pp < KSP; pp++) {
                        xz += __ldcg(&g_x6p[pp][ib]);
                        xr += __ldcg(&g_x6p[pp][ib + 512]);
                        xh += __ldcg(&g_x6p[pp][ib + 1024]);
                        iz += __ldcg(&g_i6p[pp][ib]);
                        ir += __ldcg(&g_i6p[pp][ib + 512]);
                        ih += __ldcg(&g_i6p[pp][ib + 1024]);
                    }
                    float zg = __saturatef(0.2f * (xz + iz) + 0.5f);
                    float rg = __saturatef(0.2f * (xr + ir) + 0.5f);
                    float hh = fast_tanh(xh + rg * ih);
                    float hold = (tt >= 1) ? __ldcg(&g_g6T[(size_t)(tt - 1) * HH * BB + j * BB + b]) : 0.0f;
                    g_g6T[(size_t)tt * HH * BB + j * BB + b] = zg * hold + (1.0f - zg) * hh;
                }
            }
        }
        grid_barrier(++gen);

        // ---- gemm phase: 3 matrices x 12 n-tiles(128) x 4 k-quarters = 144 ----
        if (t <= TT) {
            int g = bid / 48, r = bid % 48;
            int nt = r >> 2, part = r & 3;
            const float* AT; const float* Bm; float* C;
            if (g == 0)      { AT = g_h5T; Bm = U5; C = g_i5p[part]; }
            else if (g == 1) { AT = g_h5T; Bm = W6; C = g_x6p[part]; }
            else {
                AT = (t >= 2) ? (g_g6T + (size_t)(t - 2) * HH * BB) : g_zeroA;
                Bm = U6; C = g_i6p[part];
            }
            gemm_body(AT, BB, 0, Bm, nt * 128, C, part * 128, part * 128 + 128);
        }
        grid_barrier(++gen);
    }
}

// out[b][t] = tanh(g6[b,t,:] . Wd + bd) * dec_mask
__global__ void k_dense(const float* __restrict__ Wd, const float* __restrict__ bd,
                        const float* __restrict__ dmask, float* __restrict__ out) {
    __shared__ float wd[HH];
    int t = blockIdx.x, b = threadIdx.x;  // 128 threads
    for (int j = b; j < HH; j += 128) wd[j] = Wd[j];
    __syncthreads();
    const float* src = g_g6T + (size_t)t * HH * BB + b;
    float acc = 0.0f;
#pragma unroll 8
    for (int j = 0; j < HH; j++) acc += src[(size_t)j * BB] * wd[j];
    out[b * TT + t] = fast_tanh(acc + bd[0]) * dmask[b * TT + t];
}

// ---------------- launch ----------------
extern "C" void kernel_launch(void* const* d_in, const int* in_sizes, int n_in,
                              void* d_out, int out_size) {
    const float* z   = (const float*)d_in[0];
    const float* x2  = (const float*)d_in[1];
    const float* mk  = (const float*)d_in[2];
    const float* dmk = (const float*)d_in[3];
    const float* W5  = (const float*)d_in[4];
    const float* U5  = (const float*)d_in[5];
    const float* bi5 = (const float*)d_in[6];
    const float* br5 = (const float*)d_in[7];
    const float* W6  = (const float*)d_in[8];
    const float* U6  = (const float*)d_in[9];
    const float* bi6 = (const float*)d_in[10];
    const float* br6 = (const float*)d_in[11];
    const float* Wd  = (const float*)d_in[12];
    const float* bd  = (const float*)d_in[13];
    float* out = (float*)d_out;

    k_zero<<<256, 256>>>();
    k_build_aint<<<81920, 256>>>(z, x2, mk);
    k_gemm_x5<<<dim3(12, 512), 256>>>(W5);
    k_recur<<<NBLK, 256>>>(U5, W6, U6, bi5, br5, bi6, br6);
    k_dense<<<TT, 128>>>(Wd, bd, dmk, out);
}

// round 11
// speedup vs baseline: 1.6898x; 1.2798x over previous
#include <cuda_runtime.h>
#include <cuda_bf16.h>
#include <cstdint>

#define BB   128
#define TT   512
#define HH   512
#define H3   1536
#define LATD 256
#define F2D  64
#define DIN  320
#define MT   65536   // B*T
#define NBLK 144     // persistent grid size (<= 148 SMs, all co-resident)
#define KSP  2       // k-split for step gemms

typedef unsigned long long ull;

// ---------------- device scratch (static, no allocation) ----------------
__device__ float g_AInT[(size_t)DIN * MT];       // [320][65536] transposed masked input
__device__ float g_X5[(size_t)MT * H3];          // [B*T][1536] x@W5 (no bias)
__device__ float g_g6T[(size_t)TT * HH * BB];    // [T][H][B] GRU6 hidden archive (fp32)
__device__ float g_h5T[HH * BB];                 // [H][B] current h5 fp32 state
__device__ float g_i5p[KSP][BB * H3];            // h5 @ U5 partials
__device__ float g_x6p[KSP][BB * H3];            // h5 @ W6 partials
__device__ float g_i6p[KSP][BB * H3];            // h6 @ U6 partials
__device__ __nv_bfloat16 g_h5hi[BB * HH];        // h5 split bf16, [b][j]
__device__ __nv_bfloat16 g_h5lo[BB * HH];
__device__ __nv_bfloat16 g_h6hi[BB * HH];        // h6(t-2) split bf16, [b][j]
__device__ __nv_bfloat16 g_h6lo[BB * HH];
__device__ unsigned g_bar_count;
__device__ unsigned g_bar_release;

// ---------------- scalar helpers ----------------
__device__ __forceinline__ void fma2(ull &acc, ull a, ull b) {
    asm("fma.rn.f32x2 %0, %1, %2, %0;" : "+l"(acc) : "l"(a), "l"(b));
}
__device__ __forceinline__ ull pack2(float x) {
    ull r;
    asm("mov.b64 %0, {%1, %1};" : "=l"(r) : "r"(__float_as_uint(x)));
    return r;
}
__device__ __forceinline__ float fast_tanh(float x) {
    float y;
    asm("tanh.approx.f32 %0, %1;" : "=f"(y) : "f"(x));
    return y;
}
__device__ __forceinline__ unsigned smem_u32(const void* p) {
    unsigned r;
    asm("{ .reg .u64 t; cvta.to.shared.u64 t, %1; cvt.u32.u64 %0, t; }" : "=r"(r) : "l"(p));
    return r;
}

// ---------------- mma.sync helpers (sm_80 baseline, HMMA pipe) ----------------
__device__ __forceinline__ void ldsm4(uint32_t* r, unsigned addr) {
    asm volatile("ldmatrix.sync.aligned.m8n8.x4.shared.b16 {%0,%1,%2,%3}, [%4];"
        : "=r"(r[0]), "=r"(r[1]), "=r"(r[2]), "=r"(r[3]) : "r"(addr));
}
__device__ __forceinline__ void ldsm4t(uint32_t* r, unsigned addr) {
    asm volatile("ldmatrix.sync.aligned.m8n8.x4.trans.shared.b16 {%0,%1,%2,%3}, [%4];"
        : "=r"(r[0]), "=r"(r[1]), "=r"(r[2]), "=r"(r[3]) : "r"(addr));
}
__device__ __forceinline__ void mma16816(float* c, const uint32_t* a, uint32_t b0, uint32_t b1) {
    asm volatile(
        "mma.sync.aligned.m16n8k16.row.col.f32.bf16.bf16.f32 "
        "{%0,%1,%2,%3}, {%4,%5,%6,%7}, {%8,%9}, {%0,%1,%2,%3};"
        : "+f"(c[0]), "+f"(c[1]), "+f"(c[2]), "+f"(c[3])
        : "r"(a[0]), "r"(a[1]), "r"(a[2]), "r"(a[3]), "r"(b0), "r"(b1));
}

// ---------------- grid barrier (persistent kernel) ----------------
__device__ __forceinline__ void grid_barrier(unsigned gen) {
    __syncthreads();
    if (threadIdx.x == 0) {
        __threadfence();
        if (atomicAdd(&g_bar_count, 1u) == NBLK - 1) {
            g_bar_count = 0u;
            __threadfence();
            atomicExch(&g_bar_release, gen);
        } else {
            volatile unsigned* r = &g_bar_release;
            while ((int)(*r - gen) < 0) { }
        }
        __threadfence();
    }
    __syncthreads();
}

// ---------------- FFMA2 GEMM (kept for X5 input projection) ----------------
__device__ __forceinline__ void gemm_body(
    const float* __restrict__ AT, int lda, int gm0,
    const float* __restrict__ Bm, int gn0,
    float* __restrict__ C, int k0beg, int k0end)
{
    __shared__ __align__(16) ull   As[2][16][128];
    __shared__ __align__(16) float Bs[2][16][128];
    const int tid = threadIdx.x;
    const int tx = tid & 15;
    const int ty = tid >> 4;
    const int akk = tid >> 5;
    const int amm = (tid & 31) << 2;
    const int bkk = tid >> 4;
    const int bnn = (tid & 15) << 3;

    float4 ra0, ra1, rb0, rb1;
    ra0 = __ldcg((const float4*)&AT[(size_t)(k0beg + akk) * lda + gm0 + amm]);
    ra1 = __ldcg((const float4*)&AT[(size_t)(k0beg + akk + 8) * lda + gm0 + amm]);
    rb0 = *(const float4*)&Bm[(size_t)(k0beg + bkk) * H3 + gn0 + bnn];
    rb1 = *(const float4*)&Bm[(size_t)(k0beg + bkk) * H3 + gn0 + bnn + 4];
    {
        ulonglong2 d;
        d.x = pack2(ra0.x); d.y = pack2(ra0.y); *(ulonglong2*)&As[0][akk][amm]     = d;
        d.x = pack2(ra0.z); d.y = pack2(ra0.w); *(ulonglong2*)&As[0][akk][amm + 2] = d;
        d.x = pack2(ra1.x); d.y = pack2(ra1.y); *(ulonglong2*)&As[0][akk + 8][amm]     = d;
        d.x = pack2(ra1.z); d.y = pack2(ra1.w); *(ulonglong2*)&As[0][akk + 8][amm + 2] = d;
        *(float4*)&Bs[0][bkk][bnn]     = rb0;
        *(float4*)&Bs[0][bkk][bnn + 4] = rb1;
    }
    __syncthreads();

    ull acc[8][4];
#pragma unroll
    for (int i = 0; i < 8; i++)
#pragma unroll
        for (int j = 0; j < 4; j++) acc[i][j] = 0ULL;

    int p = 0;
    for (int k0 = k0beg; k0 < k0end; k0 += 16) {
        const bool has_next = (k0 + 16) < k0end;
        if (has_next) {
            ra0 = __ldcg((const float4*)&AT[(size_t)(k0 + 16 + akk) * lda + gm0 + amm]);
            ra1 = __ldcg((const float4*)&AT[(size_t)(k0 + 16 + akk + 8) * lda + gm0 + amm]);
            rb0 = *(const float4*)&Bm[(size_t)(k0 + 16 + bkk) * H3 + gn0 + bnn];
            rb1 = *(const float4*)&Bm[(size_t)(k0 + 16 + bkk) * H3 + gn0 + bnn + 4];
        }
#pragma unroll
        for (int kk = 0; kk < 16; kk++) {
            const ull* ap = &As[p][kk][ty << 3];
            ulonglong2 a01 = *(const ulonglong2*)(ap);
            ulonglong2 a23 = *(const ulonglong2*)(ap + 2);
            ulonglong2 a45 = *(const ulonglong2*)(ap + 4);
            ulonglong2 a67 = *(const ulonglong2*)(ap + 6);
            const ull* bp = (const ull*)&Bs[p][kk][tx << 3];
            ulonglong2 bq0 = *(const ulonglong2*)(bp);
            ulonglong2 bq1 = *(const ulonglong2*)(bp + 2);
            fma2(acc[0][0], a01.x, bq0.x); fma2(acc[0][1], a01.x, bq0.y);
            fma2(acc[0][2], a01.x, bq1.x); fma2(acc[0][3], a01.x, bq1.y);
            fma2(acc[1][0], a01.y, bq0.x); fma2(acc[1][1], a01.y, bq0.y);
            fma2(acc[1][2], a01.y, bq1.x); fma2(acc[1][3], a01.y, bq1.y);
            fma2(acc[2][0], a23.x, bq0.x); fma2(acc[2][1], a23.x, bq0.y);
            fma2(acc[2][2], a23.x, bq1.x); fma2(acc[2][3], a23.x, bq1.y);
            fma2(acc[3][0], a23.y, bq0.x); fma2(acc[3][1], a23.y, bq0.y);
            fma2(acc[3][2], a23.y, bq1.x); fma2(acc[3][3], a23.y, bq1.y);
            fma2(acc[4][0], a45.x, bq0.x); fma2(acc[4][1], a45.x, bq0.y);
            fma2(acc[4][2], a45.x, bq1.x); fma2(acc[4][3], a45.x, bq1.y);
            fma2(acc[5][0], a45.y, bq0.x); fma2(acc[5][1], a45.y, bq0.y);
            fma2(acc[5][2], a45.y, bq1.x); fma2(acc[5][3], a45.y, bq1.y);
            fma2(acc[6][0], a67.x, bq0.x); fma2(acc[6][1], a67.x, bq0.y);
            fma2(acc[6][2], a67.x, bq1.x); fma2(acc[6][3], a67.x, bq1.y);
            fma2(acc[7][0], a67.y, bq0.x); fma2(acc[7][1], a67.y, bq0.y);
            fma2(acc[7][2], a67.y, bq1.x); fma2(acc[7][3], a67.y, bq1.y);
        }
        if (has_next) {
            const int q = p ^ 1;
            ulonglong2 d;
            d.x = pack2(ra0.x); d.y = pack2(ra0.y); *(ulonglong2*)&As[q][akk][amm]     = d;
            d.x = pack2(ra0.z); d.y = pack2(ra0.w); *(ulonglong2*)&As[q][akk][amm + 2] = d;
            d.x = pack2(ra1.x); d.y = pack2(ra1.y); *(ulonglong2*)&As[q][akk + 8][amm]     = d;
            d.x = pack2(ra1.z); d.y = pack2(ra1.w); *(ulonglong2*)&As[q][akk + 8][amm + 2] = d;
            *(float4*)&Bs[q][bkk][bnn]     = rb0;
            *(float4*)&Bs[q][bkk][bnn + 4] = rb1;
        }
        __syncthreads();
        p ^= 1;
    }
#pragma unroll
    for (int i = 0; i < 8; i++) {
        float2 p0 = *(float2*)&acc[i][0];
        float2 p1 = *(float2*)&acc[i][1];
        float2 p2 = *(float2*)&acc[i][2];
        float2 p3 = *(float2*)&acc[i][3];
        int m = gm0 + (ty << 3) + i;
        *(float4*)&C[(size_t)m * H3 + gn0 + (tx << 3)]     = make_float4(p0.x, p0.y, p1.x, p1.y);
        *(float4*)&C[(size_t)m * H3 + gn0 + (tx << 3) + 4] = make_float4(p2.x, p2.y, p3.x, p3.y);
    }
}

// ---------------- small kernels ----------------
__global__ void k_zero() {
    if (threadIdx.x == 0) { g_bar_count = 0u; g_bar_release = 0u; }
}

__global__ void k_build_aint(const float* __restrict__ z,
                             const float* __restrict__ x2,
                             const float* __restrict__ masks) {
    int idx = blockIdx.x * 256 + threadIdx.x;      // 320*65536 exact
    int k = idx >> 16, m = idx & 65535;
    int b = m >> 9;
    float v = (k < LATD) ? z[(b << 8) + k] : x2[(size_t)m * F2D + (k - LATD)];
    g_AInT[idx] = v * masks[m];
}

__global__ void __launch_bounds__(256) k_gemm_x5(const float* __restrict__ W5) {
    gemm_body(g_AInT, MT, blockIdx.y * 128, W5, blockIdx.x * 128, g_X5, 0, DIN);
}

// ---------------- persistent recurrence kernel (mma.sync bf16) ----------------
// A tiles: [m=128][k=256] bf16, pitch 264 (=33 uint4)  -> 67584 B each
// B tiles: [k=256][n=64]  bf16, pitch 72               -> 36864 B each
#define PA 264
#define PB 72
#define SM_A_HI 0
#define SM_A_LO 67584
#define SM_B_HI 135168
#define SM_B_LO 172032
#define SMEM_DYN (208896 + 1024)

__global__ void __launch_bounds__(256, 1)
k_recur(const float* __restrict__ U5, const float* __restrict__ W6,
        const float* __restrict__ U6,
        const float* __restrict__ bi5, const float* __restrict__ br5,
        const float* __restrict__ bi6, const float* __restrict__ br6)
{
    extern __shared__ char dsm_raw[];
    char* dsm = (char*)(((uintptr_t)dsm_raw + 1023) & ~(uintptr_t)1023);
    const unsigned sb = smem_u32(dsm);

    const int tid = threadIdx.x, wid = tid >> 5, lid = tid & 31, bid = blockIdx.x;

    // ---- static work assignment ----
    const int g  = bid / 48;          // 0: U5, 1: W6, 2: U6
    const int r  = bid % 48;
    const int nt = r >> 1;            // 24 n-tiles of 64
    const int kh = r & 1;             // 2 k-halves of 256
    const int gn0 = nt * 64, k0 = kh * 256;
    const float* Wm = (g == 0) ? U5 : ((g == 1) ? W6 : U6);
    float* Cp = (g == 0) ? g_i5p[kh] : ((g == 1) ? g_x6p[kh] : g_i6p[kh]);
    const uint4* Ahs = (const uint4*)((g == 2) ? g_h6hi : g_h5hi);
    const uint4* Als = (const uint4*)((g == 2) ? g_h6lo : g_h5lo);

    // ---- stage B (weights, split hi/lo) once; persists across all steps ----
    for (int v = tid; v < 256 * 64; v += 256) {
        int k = v >> 6, n = v & 63;
        float w = Wm[(size_t)(k0 + k) * H3 + gn0 + n];
        __nv_bfloat16 hi = __float2bfloat16_rn(w);
        __nv_bfloat16 lo = __float2bfloat16_rn(w - __bfloat162float(hi));
        int off = (k * PB + n) * 2;
        *(__nv_bfloat16*)(dsm + SM_B_HI + off) = hi;
        *(__nv_bfloat16*)(dsm + SM_B_LO + off) = lo;
    }

    // ---- per-thread ldmatrix base addresses ----
    const int wm = wid & 3;           // m-quadrant (32 rows)
    const int wn = wid >> 2;          // n-half (32 cols)
    // A: lanes 0-15 -> rows m0..m15 @k0 ; lanes 16-31 -> same rows @k0+8
    unsigned aHiB[2], aLoB[2];
#pragma unroll
    for (int mi = 0; mi < 2; mi++) {
        unsigned off = (unsigned)(((wm * 32 + mi * 16 + (lid & 15)) * PA + ((lid >> 4) * 8)) * 2);
        aHiB[mi] = sb + SM_A_HI + off;
        aLoB[mi] = sb + SM_A_LO + off;
    }
    // B (trans): lanes 0-7 -> k0..7 @n ; 8-15 -> k8..15 @n ; 16-31 same @n+8
    unsigned bHiB[2], bLoB[2];
#pragma unroll
    for (int nq = 0; nq < 2; nq++) {
        unsigned off = (unsigned)((((lid & 7) + ((lid >> 3) & 1) * 8) * PB
                                   + wn * 32 + nq * 16 + (lid >> 4) * 8) * 2);
        bHiB[nq] = sb + SM_B_HI + off;
        bLoB[nq] = sb + SM_B_LO + off;
    }

    unsigned gen = 0;
    for (int t = 0; t <= TT + 1; ++t) {
        // ---- gates phase ----
        for (int idx = bid * 256 + tid; idx < 2 * 65536; idx += NBLK * 256) {
            int part = idx >> 16;
            int i = idx & 65535;
            int b = i >> 9, j = i & 511;
            if (part == 0) {
                if (t == 0) {
                    g_h5T[j * BB + b] = 0.0f;
                    g_h5hi[i] = __float2bfloat16_rn(0.0f);
                    g_h5lo[i] = __float2bfloat16_rn(0.0f);
                } else if (t <= TT) {
                    int tt = t - 1;
                    size_t xb = ((size_t)(b * TT + tt)) * H3 + j;
                    float xz = g_X5[xb]        + bi5[j];
                    float xr = g_X5[xb + 512]  + bi5[512 + j];
                    float xh = g_X5[xb + 1024] + bi5[1024 + j];
                    int ib = b * H3 + j;
                    float iz = br5[j], ir = br5[512 + j], ih = br5[1024 + j];
#pragma unroll
                    for (int pp = 0; pp < KSP; pp++) {
                        iz += __ldcg(&g_i5p[pp][ib]);
                        ir += __ldcg(&g_i5p[pp][ib + 512]);
                        ih += __ldcg(&g_i5p[pp][ib + 1024]);
                    }
                    float zg = __saturatef(0.2f * (xz + iz) + 0.5f);
                    float rg = __saturatef(0.2f * (xr + ir) + 0.5f);
                    float hh = fast_tanh(xh + rg * ih);
                    float hold = __ldcg(&g_h5T[j * BB + b]);
                    float hn = zg * hold + (1.0f - zg) * hh;
                    g_h5T[j * BB + b] = hn;
                    __nv_bfloat16 hi = __float2bfloat16_rn(hn);
                    g_h5hi[i] = hi;
                    g_h5lo[i] = __float2bfloat16_rn(hn - __bfloat162float(hi));
                }
            } else {
                if (t < 2) {
                    g_h6hi[i] = __float2bfloat16_rn(0.0f);
                    g_h6lo[i] = __float2bfloat16_rn(0.0f);
                } else {
                    int tt = t - 2;
                    int ib = b * H3 + j;
                    float xz = bi6[j], xr = bi6[512 + j], xh = bi6[1024 + j];
                    float iz = br6[j], ir = br6[512 + j], ih = br6[1024 + j];
#pragma unroll
                    for (int pp = 0; pp < KSP; pp++) {
                        xz += __ldcg(&g_x6p[pp][ib]);
                        xr += __ldcg(&g_x6p[pp][ib + 512]);
                        xh += __ldcg(&g_x6p[pp][ib + 1024]);
                        iz += __ldcg(&g_i6p[pp][ib]);
                        ir += __ldcg(&g_i6p[pp][ib + 512]);
                        ih += __ldcg(&g_i6p[pp][ib + 1024]);
                    }
                    float zg = __saturatef(0.2f * (xz + iz) + 0.5f);
                    float rg = __saturatef(0.2f * (xr + ir) + 0.5f);
                    float hh = fast_tanh(xh + rg * ih);
                    float hold = (tt >= 1) ? __ldcg(&g_g6T[(size_t)(tt - 1) * HH * BB + j * BB + b]) : 0.0f;
                    float hn = zg * hold + (1.0f - zg) * hh;
                    g_g6T[(size_t)tt * HH * BB + j * BB + b] = hn;
                    __nv_bfloat16 hi = __float2bfloat16_rn(hn);
                    g_h6hi[i] = hi;
                    g_h6lo[i] = __float2bfloat16_rn(hn - __bfloat162float(hi));
                }
            }
        }
        grid_barrier(++gen);

        // ---- gemm phase (mma.sync bf16, 3-term split) ----
        if (t <= TT) {
            // stage A: h[m][k0..k0+255] hi/lo -> smem pitch PA (33 uint4/row)
            for (int v = tid; v < 4096; v += 256) {
                int m = v >> 5, c = v & 31;
                int si = m * 64 + kh * 32 + c;
                ((uint4*)(dsm + SM_A_HI))[m * 33 + c] = __ldcg(Ahs + si);
                ((uint4*)(dsm + SM_A_LO))[m * 33 + c] = __ldcg(Als + si);
            }
            __syncthreads();

            float acc[2][4][4];
#pragma unroll
            for (int mi = 0; mi < 2; mi++)
#pragma unroll
                for (int nq = 0; nq < 4; nq++)
#pragma unroll
                    for (int e = 0; e < 4; e++) acc[mi][nq][e] = 0.0f;

            unsigned a0 = aHiB[0], a1 = aHiB[1], a2 = aLoB[0], a3 = aLoB[1];
            unsigned b0 = bHiB[0], b1 = bHiB[1], b2 = bLoB[0], b3 = bLoB[1];
#pragma unroll 2
            for (int k16 = 0; k16 < 16; k16++) {
                uint32_t Ah[2][4], Al[2][4], Bh[2][4], Bl[2][4];
                ldsm4(Ah[0], a0); ldsm4(Ah[1], a1);
                ldsm4(Al[0], a2); ldsm4(Al[1], a3);
                ldsm4t(Bh[0], b0); ldsm4t(Bh[1], b1);
                ldsm4t(Bl[0], b2); ldsm4t(Bl[1], b3);
                a0 += 32; a1 += 32; a2 += 32; a3 += 32;
                b0 += 16 * PB * 2; b1 += 16 * PB * 2; b2 += 16 * PB * 2; b3 += 16 * PB * 2;
#pragma unroll
                for (int mi = 0; mi < 2; mi++) {
#pragma unroll
                    for (int nq = 0; nq < 4; nq++) {
                        uint32_t bh0 = Bh[nq >> 1][(nq & 1) * 2], bh1 = Bh[nq >> 1][(nq & 1) * 2 + 1];
                        uint32_t bl0 = Bl[nq >> 1][(nq & 1) * 2], bl1 = Bl[nq >> 1][(nq & 1) * 2 + 1];
                        mma16816(acc[mi][nq], Ah[mi], bh0, bh1);   // hi*hi
                        mma16816(acc[mi][nq], Ah[mi], bl0, bl1);   // hi*lo
                        mma16816(acc[mi][nq], Al[mi], bh0, bh1);   // lo*hi
                    }
                }
            }

            // epilogue: write C fragments to partials
#pragma unroll
            for (int mi = 0; mi < 2; mi++) {
                int rbase = wm * 32 + mi * 16 + (lid >> 2);
#pragma unroll
                for (int nq = 0; nq < 4; nq++) {
                    int col = gn0 + wn * 32 + nq * 8 + (lid & 3) * 2;
                    *(float2*)&Cp[(size_t)rbase * H3 + col] =
                        make_float2(acc[mi][nq][0], acc[mi][nq][1]);
                    *(float2*)&Cp[(size_t)(rbase + 8) * H3 + col] =
                        make_float2(acc[mi][nq][2], acc[mi][nq][3]);
                }
            }
        }
        grid_barrier(++gen);
    }
}

// out[b][t] = tanh(g6[b,t,:] . Wd + bd) * dec_mask
__global__ void k_dense(const float* __restrict__ Wd, const float* __restrict__ bd,
                        const float* __restrict__ dmask, float* __restrict__ out) {
    __shared__ float wd[HH];
    int t = blockIdx.x, b = threadIdx.x;  // 128 threads
    for (int j = b; j < HH; j += 128) wd[j] = Wd[j];
    __syncthreads();
    const float* src = g_g6T + (size_t)t * HH * BB + b;
    float acc = 0.0f;
#pragma unroll 8
    for (int j = 0; j < HH; j++) acc += src[(size_t)j * BB] * wd[j];
    out[b * TT + t] = fast_tanh(acc + bd[0]) * dmask[b * TT + t];
}

// ---------------- launch ----------------
extern "C" void kernel_launch(void* const* d_in, const int* in_sizes, int n_in,
                              void* d_out, int out_size) {
    const float* z   = (const float*)d_in[0];
    const float* x2  = (const float*)d_in[1];
    const float* mk  = (const float*)d_in[2];
    const float* dmk = (const float*)d_in[3];
    const float* W5  = (const float*)d_in[4];
    const float* U5  = (const float*)d_in[5];
    const float* bi5 = (const float*)d_in[6];
    const float* br5 = (const float*)d_in[7];
    const float* W6  = (const float*)d_in[8];
    const float* U6  = (const float*)d_in[9];
    const float* bi6 = (const float*)d_in[10];
    const float* br6 = (const float*)d_in[11];
    const float* Wd  = (const float*)d_in[12];
    const float* bd  = (const float*)d_in[13];
    float* out = (float*)d_out;

    cudaFuncSetAttribute(k_recur, cudaFuncAttributeMaxDynamicSharedMemorySize, SMEM_DYN);

    k_zero<<<1, 32>>>();
    k_build_aint<<<81920, 256>>>(z, x2, mk);
    k_gemm_x5<<<dim3(12, 512), 256>>>(W5);
    k_recur<<<NBLK, 256, SMEM_DYN>>>(U5, W6, U6, bi5, br5, bi6, br6);
    k_dense<<<TT, 128>>>(Wd, bd, dmk, out);
}

// round 13
// speedup vs baseline: 2.4337x; 1.4403x over previous
#include <cuda_runtime.h>
#include <cuda_bf16.h>
#include <cstdint>

#define BB   128
#define TT   512
#define HH   512
#define H3   1536
#define LATD 256
#define F2D  64
#define DIN  320
#define MT   65536   // B*T
#define NBLK 144     // persistent grid size (<= 148 SMs, all co-resident)
#define KSP  2       // k-split for step gemms
#define RTH  512     // threads per block in k_recur

typedef unsigned long long ull;

// ---------------- device scratch (static, no allocation) ----------------
__device__ __nv_bfloat16 g_Xhi[(size_t)MT * DIN]; // masked input split hi [m][320]
__device__ __nv_bfloat16 g_Xlo[(size_t)MT * DIN];
__device__ float g_X5[(size_t)MT * H3];          // [B*T][1536] x@W5 (no bias)
__device__ float g_g6T[(size_t)TT * HH * BB];    // [T][H][B] GRU6 hidden archive (fp32)
__device__ float g_h5T[HH * BB];                 // [H][B] current h5 fp32 state
__device__ float g_i5p[KSP][BB * H3];            // h5 @ U5 partials
__device__ float g_x6p[KSP][BB * H3];            // h5 @ W6 partials
__device__ float g_i6p[KSP][BB * H3];            // h6 @ U6 partials
__device__ __nv_bfloat16 g_h5hi[BB * HH];        // h5 split bf16, [b][j]
__device__ __nv_bfloat16 g_h5lo[BB * HH];
__device__ __nv_bfloat16 g_h6hi[BB * HH];        // h6(t-2) split bf16, [b][j]
__device__ __nv_bfloat16 g_h6lo[BB * HH];
__device__ unsigned g_bar_count;
__device__ unsigned g_bar_release;

// ---------------- scalar helpers ----------------
__device__ __forceinline__ float fast_tanh(float x) {
    float y;
    asm("tanh.approx.f32 %0, %1;" : "=f"(y) : "f"(x));
    return y;
}
__device__ __forceinline__ unsigned smem_u32(const void* p) {
    unsigned r;
    asm("{ .reg .u64 t; cvta.to.shared.u64 t, %1; cvt.u32.u64 %0, t; }" : "=r"(r) : "l"(p));
    return r;
}

// ---------------- mma.sync helpers (sm_80 baseline, HMMA pipe) ----------------
__device__ __forceinline__ void ldsm4(uint32_t* r, unsigned addr) {
    asm volatile("ldmatrix.sync.aligned.m8n8.x4.shared.b16 {%0,%1,%2,%3}, [%4];"
        : "=r"(r[0]), "=r"(r[1]), "=r"(r[2]), "=r"(r[3]) : "r"(addr));
}
__device__ __forceinline__ void ldsm4t(uint32_t* r, unsigned addr) {
    asm volatile("ldmatrix.sync.aligned.m8n8.x4.trans.shared.b16 {%0,%1,%2,%3}, [%4];"
        : "=r"(r[0]), "=r"(r[1]), "=r"(r[2]), "=r"(r[3]) : "r"(addr));
}
__device__ __forceinline__ void mma16816(float* c, const uint32_t* a, uint32_t b0, uint32_t b1) {
    asm volatile(
        "mma.sync.aligned.m16n8k16.row.col.f32.bf16.bf16.f32 "
        "{%0,%1,%2,%3}, {%4,%5,%6,%7}, {%8,%9}, {%0,%1,%2,%3};"
        : "+f"(c[0]), "+f"(c[1]), "+f"(c[2]), "+f"(c[3])
        : "r"(a[0]), "r"(a[1]), "r"(a[2]), "r"(a[3]), "r"(b0), "r"(b1));
}
__device__ __forceinline__ void bsplit(float v, __nv_bfloat16& hi, __nv_bfloat16& lo) {
    hi = __float2bfloat16_rn(v);
    lo = __float2bfloat16_rn(v - __bfloat162float(hi));
}

// ---------------- grid barrier (persistent kernel) ----------------
__device__ __forceinline__ void grid_barrier(unsigned gen) {
    __syncthreads();
    if (threadIdx.x == 0) {
        __threadfence();
        if (atomicAdd(&g_bar_count, 1u) == NBLK - 1) {
            g_bar_count = 0u;
            __threadfence();
            atomicExch(&g_bar_release, gen);
        } else {
            volatile unsigned* r = &g_bar_release;
            while ((int)(*r - gen) < 0) { }
        }
        __threadfence();
    }
    __syncthreads();
}

// ---------------- small kernels ----------------
__global__ void k_zero() {
    if (threadIdx.x == 0) { g_bar_count = 0u; g_bar_release = 0u; }
}

// build masked input, split to bf16 hi/lo: [m][k], k<320
__global__ void k_build(const float* __restrict__ z,
                        const float* __restrict__ x2,
                        const float* __restrict__ masks) {
    int m = blockIdx.x, k = threadIdx.x;   // grid 65536, block 320
    int b = m >> 9;
    float v = (k < LATD) ? z[(b << 8) + k] : x2[(size_t)m * F2D + (k - LATD)];
    v *= masks[m];
    __nv_bfloat16 hi, lo;
    bsplit(v, hi, lo);
    g_Xhi[(size_t)m * DIN + k] = hi;
    g_Xlo[(size_t)m * DIN + k] = lo;
}

// ---------------- X5 input projection: mma.sync bf16 3-term ----------------
// C[128m x 64n] = X[m][320] @ W5[320][n], block grid (24 n, 512 m)
#define XPB 72
#define XPA 72
#define XS_B_HI 0
#define XS_B_LO 46080
#define XS_A_HI0 92160
#define XS_A_HI1 110592
#define XS_A_LO0 129024
#define XS_A_LO1 147456
#define XS_TOTAL 165888

__global__ void __launch_bounds__(256, 1)
k_x5(const float* __restrict__ W5) {
    extern __shared__ char xsm[];
    const unsigned sb = smem_u32(xsm);
    const int tid = threadIdx.x, wid = tid >> 5, lid = tid & 31;
    const int gn0 = blockIdx.x * 64, gm0 = blockIdx.y * 128;
    const int wm = wid & 3, wn = wid >> 2;

    // stage B (hi/lo) [k=320][n=64], pitch 72
    for (int v = tid; v < 320 * 64; v += 256) {
        int k = v >> 6, n = v & 63;
        float w = W5[(size_t)k * H3 + gn0 + n];
        __nv_bfloat16 hi, lo; bsplit(w, hi, lo);
        int off = (k * XPB + n) * 2;
        *(__nv_bfloat16*)(xsm + XS_B_HI + off) = hi;
        *(__nv_bfloat16*)(xsm + XS_B_LO + off) = lo;
    }

    const unsigned ah_buf[2] = { sb + XS_A_HI0, sb + XS_A_HI1 };
    const unsigned al_buf[2] = { sb + XS_A_LO0, sb + XS_A_LO1 };
    const unsigned a_off[2] = {
        (unsigned)(((wm * 32 +  0 + (lid & 15)) * XPA + (lid >> 4) * 8) * 2),
        (unsigned)(((wm * 32 + 16 + (lid & 15)) * XPA + (lid >> 4) * 8) * 2) };
    const unsigned b_off[2] = {
        (unsigned)((((lid & 7) + ((lid >> 3) & 1) * 8) * XPB + wn * 32 +  0 + (lid >> 4) * 8) * 2),
        (unsigned)((((lid & 7) + ((lid >> 3) & 1) * 8) * XPB + wn * 32 + 16 + (lid >> 4) * 8) * 2) };

    float acc[2][4][4];
#pragma unroll
    for (int mi = 0; mi < 2; mi++)
#pragma unroll
        for (int nq = 0; nq < 4; nq++)
#pragma unroll
            for (int e = 0; e < 4; e++) acc[mi][nq][e] = 0.0f;

    const uint4* XH = (const uint4*)g_Xhi;
    const uint4* XL = (const uint4*)g_Xlo;

    for (int c = 0; c < 5; c++) {            // 5 chunks of k64
        int p = c & 1;
        char* ah = xsm + (p ? XS_A_HI1 : XS_A_HI0);
        char* al = xsm + (p ? XS_A_LO1 : XS_A_LO0);
        // stage A chunk: 128 rows x 8 uint4 (64 bf16), pitch 9 uint4
        for (int v = tid; v < 1024; v += 256) {
            int m = v >> 3, c8 = v & 7;
            size_t si = (size_t)(gm0 + m) * 40 + c * 8 + c8;   // 40 uint4 per 320-row
            ((uint4*)ah)[m * 9 + c8] = __ldcg(XH + si);
            ((uint4*)al)[m * 9 + c8] = __ldcg(XL + si);
        }
        __syncthreads();
#pragma unroll
        for (int k16 = 0; k16 < 4; k16++) {
            int kk = c * 4 + k16;
            uint32_t Ah[2][4], Al[2][4], Bh[2][4], Bl[2][4];
#pragma unroll
            for (int mi = 0; mi < 2; mi++) {
                ldsm4(Ah[mi], ah_buf[p] + a_off[mi] + k16 * 32);
                ldsm4(Al[mi], al_buf[p] + a_off[mi] + k16 * 32);
            }
#pragma unroll
            for (int nq = 0; nq < 2; nq++) {
                ldsm4t(Bh[nq], sb + XS_B_HI + b_off[nq] + kk * 16 * XPB * 2);
                ldsm4t(Bl[nq], sb + XS_B_LO + b_off[nq] + kk * 16 * XPB * 2);
            }
#pragma unroll
            for (int mi = 0; mi < 2; mi++) {
#pragma unroll
                for (int nq = 0; nq < 4; nq++) {
                    uint32_t bh0 = Bh[nq >> 1][(nq & 1) * 2], bh1 = Bh[nq >> 1][(nq & 1) * 2 + 1];
                    uint32_t bl0 = Bl[nq >> 1][(nq & 1) * 2], bl1 = Bl[nq >> 1][(nq & 1) * 2 + 1];
                    mma16816(acc[mi][nq], Ah[mi], bh0, bh1);
                    mma16816(acc[mi][nq], Ah[mi], bl0, bl1);
                    mma16816(acc[mi][nq], Al[mi], bh0, bh1);
                }
            }
        }
    }
#pragma unroll
    for (int mi = 0; mi < 2; mi++) {
        int rbase = gm0 + wm * 32 + mi * 16 + (lid >> 2);
#pragma unroll
        for (int nq = 0; nq < 4; nq++) {
            int col = gn0 + wn * 32 + nq * 8 + (lid & 3) * 2;
            *(float2*)&g_X5[(size_t)rbase * H3 + col] = make_float2(acc[mi][nq][0], acc[mi][nq][1]);
            *(float2*)&g_X5[(size_t)(rbase + 8) * H3 + col] = make_float2(acc[mi][nq][2], acc[mi][nq][3]);
        }
    }
}

// ---------------- persistent recurrence kernel (mma.sync bf16) ----------------
// A tiles: [m=128][k=256] bf16, pitch 264 (=33 uint4)  -> 67584 B each
// B tiles: [k=256][n=64]  bf16, pitch 72               -> 36864 B each
#define PA 264
#define PB 72
#define SM_A_HI 0
#define SM_A_LO 67584
#define SM_B_HI 135168
#define SM_B_LO 172032
#define SMEM_DYN 208896

__global__ void __launch_bounds__(RTH, 1)
k_recur(const float* __restrict__ U5, const float* __restrict__ W6,
        const float* __restrict__ U6,
        const float* __restrict__ bi5, const float* __restrict__ br5,
        const float* __restrict__ bi6, const float* __restrict__ br6)
{
    extern __shared__ char dsm[];
    const unsigned sb = smem_u32(dsm);

    const int tid = threadIdx.x, wid = tid >> 5, lid = tid & 31, bid = blockIdx.x;

    // ---- static work assignment ----
    const int g  = bid / 48;          // 0: U5, 1: W6, 2: U6
    const int r  = bid % 48;
    const int nt = r >> 1;            // 24 n-tiles of 64
    const int kh = r & 1;             // 2 k-halves of 256
    const int gn0 = nt * 64, k0 = kh * 256;
    const float* Wm = (g == 0) ? U5 : ((g == 1) ? W6 : U6);
    float* Cp = (g == 0) ? g_i5p[kh] : ((g == 1) ? g_x6p[kh] : g_i6p[kh]);
    const uint4* Ahs = (const uint4*)((g == 2) ? g_h6hi : g_h5hi);
    const uint4* Als = (const uint4*)((g == 2) ? g_h6lo : g_h5lo);

    // ---- stage B (weights, split hi/lo) once; persists across all steps ----
    for (int v = tid; v < 256 * 64; v += RTH) {
        int k = v >> 6, n = v & 63;
        float w = Wm[(size_t)(k0 + k) * H3 + gn0 + n];
        __nv_bfloat16 hi, lo; bsplit(w, hi, lo);
        int off = (k * PB + n) * 2;
        *(__nv_bfloat16*)(dsm + SM_B_HI + off) = hi;
        *(__nv_bfloat16*)(dsm + SM_B_LO + off) = lo;
    }

    // ---- per-thread ldmatrix base addresses (16 warps: 8m x 2n) ----
    const int wm = wid & 7;           // m-slice (16 rows)
    const int wn = wid >> 3;          // n-half (32 cols)
    const unsigned aOff = (unsigned)(((wm * 16 + (lid & 15)) * PA + (lid >> 4) * 8) * 2);
    const unsigned aHiB = sb + SM_A_HI + aOff;
    const unsigned aLoB = sb + SM_A_LO + aOff;
    unsigned bHiB[2], bLoB[2];
#pragma unroll
    for (int nq = 0; nq < 2; nq++) {
        unsigned off = (unsigned)((((lid & 7) + ((lid >> 3) & 1) * 8) * PB
                                   + wn * 32 + nq * 16 + (lid >> 4) * 8) * 2);
        bHiB[nq] = sb + SM_B_HI + off;
        bLoB[nq] = sb + SM_B_LO + off;
    }

    unsigned gen = 0;
    for (int t = 0; t <= TT + 1; ++t) {
        // ---- gates phase ----
        for (int idx = bid * RTH + tid; idx < 2 * 65536; idx += NBLK * RTH) {
            int part = idx >> 16;
            int i = idx & 65535;
            int b = i >> 9, j = i & 511;
            if (part == 0) {
                if (t == 0) {
                    g_h5T[j * BB + b] = 0.0f;
                    g_h5hi[i] = __float2bfloat16_rn(0.0f);
                    g_h5lo[i] = __float2bfloat16_rn(0.0f);
                } else if (t <= TT) {
                    int tt = t - 1;
                    size_t xb = ((size_t)(b * TT + tt)) * H3 + j;
                    float xz = g_X5[xb]        + bi5[j];
                    float xr = g_X5[xb + 512]  + bi5[512 + j];
                    float xh = g_X5[xb + 1024] + bi5[1024 + j];
                    int ib = b * H3 + j;
                    float iz = br5[j], ir = br5[512 + j], ih = br5[1024 + j];
#pragma unroll
                    for (int pp = 0; pp < KSP; pp++) {
                        iz += __ldcg(&g_i5p[pp][ib]);
                        ir += __ldcg(&g_i5p[pp][ib + 512]);
                        ih += __ldcg(&g_i5p[pp][ib + 1024]);
                    }
                    float zg = __saturatef(0.2f * (xz + iz) + 0.5f);
                    float rg = __saturatef(0.2f * (xr + ir) + 0.5f);
                    float hh = fast_tanh(xh + rg * ih);
                    float hold = __ldcg(&g_h5T[j * BB + b]);
                    float hn = zg * hold + (1.0f - zg) * hh;
                    g_h5T[j * BB + b] = hn;
                    __nv_bfloat16 hi, lo; bsplit(hn, hi, lo);
                    g_h5hi[i] = hi;
                    g_h5lo[i] = lo;
                }
            } else {
                if (t < 2) {
                    g_h6hi[i] = __float2bfloat16_rn(0.0f);
                    g_h6lo[i] = __float2bfloat16_rn(0.0f);
                } else {
                    int tt = t - 2;
                    int ib = b * H3 + j;
                    float xz = bi6[j], xr = bi6[512 + j], xh = bi6[1024 + j];
                    float iz = br6[j], ir = br6[512 + j], ih = br6[1024 + j];
#pragma unroll
                    for (int pp = 0; pp < KSP; pp++) {
                        xz += __ldcg(&g_x6p[pp][ib]);
                        xr += __ldcg(&g_x6p[pp][ib + 512]);
                        xh += __ldcg(&g_x6p[pp][ib + 1024]);
                        iz += __ldcg(&g_i6p[pp][ib]);
                        ir += __ldcg(&g_i6p[pp][ib + 512]);
                        ih += __ldcg(&g_i6p[pp][ib + 1024]);
                    }
                    float zg = __saturatef(0.2f * (xz + iz) + 0.5f);
                    float rg = __saturatef(0.2f * (xr + ir) + 0.5f);
                    float hh = fast_tanh(xh + rg * ih);
                    float hold = (tt >= 1) ? __ldcg(&g_g6T[(size_t)(tt - 1) * HH * BB + j * BB + b]) : 0.0f;
                    float hn = zg * hold + (1.0f - zg) * hh;
                    g_g6T[(size_t)tt * HH * BB + j * BB + b] = hn;
                    __nv_bfloat16 hi, lo; bsplit(hn, hi, lo);
                    g_h6hi[i] = hi;
                    g_h6lo[i] = lo;
                }
            }
        }
        grid_barrier(++gen);

        // ---- gemm phase (mma.sync bf16, 3-term split) ----
        if (t <= TT) {
            // stage A: h[m][k0..k0+255] hi/lo -> smem pitch PA (33 uint4/row)
            for (int v = tid; v < 4096; v += RTH) {
                int m = v >> 5, c = v & 31;
                int si = m * 64 + kh * 32 + c;
                ((uint4*)(dsm + SM_A_HI))[m * 33 + c] = __ldcg(Ahs + si);
                ((uint4*)(dsm + SM_A_LO))[m * 33 + c] = __ldcg(Als + si);
            }
            // L2 prefetch of next step's X5 slice (rows b*TT + t)
            if (t < TT) {
                int v = bid * RTH + tid;
                if (v < 12288) {
                    int b = v / 96, ln = v % 96;
                    const float* pf = &g_X5[(size_t)(b * TT + t) * H3 + ln * 16];
                    asm volatile("prefetch.global.L2 [%0];" :: "l"(pf));
                }
            }
            __syncthreads();

            float acc[4][4];
#pragma unroll
            for (int nq = 0; nq < 4; nq++)
#pragma unroll
                for (int e = 0; e < 4; e++) acc[nq][e] = 0.0f;

            unsigned a0 = aHiB, a1 = aLoB;
            unsigned b0 = bHiB[0], b1 = bHiB[1], b2 = bLoB[0], b3 = bLoB[1];
#pragma unroll 4
            for (int k16 = 0; k16 < 16; k16++) {
                uint32_t Ah[4], Al[4], Bh[2][4], Bl[2][4];
                ldsm4(Ah, a0); ldsm4(Al, a1);
                ldsm4t(Bh[0], b0); ldsm4t(Bh[1], b1);
                ldsm4t(Bl[0], b2); ldsm4t(Bl[1], b3);
                a0 += 32; a1 += 32;
                b0 += 16 * PB * 2; b1 += 16 * PB * 2; b2 += 16 * PB * 2; b3 += 16 * PB * 2;
#pragma unroll
                for (int nq = 0; nq < 4; nq++) {
                    uint32_t bh0 = Bh[nq >> 1][(nq & 1) * 2], bh1 = Bh[nq >> 1][(nq & 1) * 2 + 1];
                    uint32_t bl0 = Bl[nq >> 1][(nq & 1) * 2], bl1 = Bl[nq >> 1][(nq & 1) * 2 + 1];
                    mma16816(acc[nq], Ah, bh0, bh1);   // hi*hi
                    mma16816(acc[nq], Ah, bl0, bl1);   // hi*lo
                    mma16816(acc[nq], Al, bh0, bh1);   // lo*hi
                }
            }

            // epilogue: write C fragments to partials
            int rbase = wm * 16 + (lid >> 2);
#pragma unroll
            for (int nq = 0; nq < 4; nq++) {
                int col = gn0 + wn * 32 + nq * 8 + (lid & 3) * 2;
                *(float2*)&Cp[(size_t)rbase * H3 + col] = make_float2(acc[nq][0], acc[nq][1]);
                *(float2*)&Cp[(size_t)(rbase + 8) * H3 + col] = make_float2(acc[nq][2], acc[nq][3]);
            }
        }
        grid_barrier(++gen);
    }
}

// out[b][t] = tanh(g6[b,t,:] . Wd + bd) * dec_mask
__global__ void k_dense(const float* __restrict__ Wd, const float* __restrict__ bd,
                        const float* __restrict__ dmask, float* __restrict__ out) {
    __shared__ float wd[HH];
    int t = blockIdx.x, b = threadIdx.x;  // 128 threads
    for (int j = b; j < HH; j += 128) wd[j] = Wd[j];
    __syncthreads();
    const float* src = g_g6T + (size_t)t * HH * BB + b;
    float acc = 0.0f;
#pragma unroll 8
    for (int j = 0; j < HH; j++) acc += src[(size_t)j * BB] * wd[j];
    out[b * TT + t] = fast_tanh(acc + bd[0]) * dmask[b * TT + t];
}

// ---------------- launch ----------------
extern "C" void kernel_launch(void* const* d_in, const int* in_sizes, int n_in,
                              void* d_out, int out_size) {
    const float* z   = (const float*)d_in[0];
    const float* x2  = (const float*)d_in[1];
    const float* mk  = (const float*)d_in[2];
    const float* dmk = (const float*)d_in[3];
    const float* W5  = (const float*)d_in[4];
    const float* U5  = (const float*)d_in[5];
    const float* bi5 = (const float*)d_in[6];
    const float* br5 = (const float*)d_in[7];
    const float* W6  = (const float*)d_in[8];
    const float* U6  = (const float*)d_in[9];
    const float* bi6 = (const float*)d_in[10];
    const float* br6 = (const float*)d_in[11];
    const float* Wd  = (const float*)d_in[12];
    const float* bd  = (const float*)d_in[13];
    float* out = (float*)d_out;

    cudaFuncSetAttribute(k_recur, cudaFuncAttributeMaxDynamicSharedMemorySize, SMEM_DYN);
    cudaFuncSetAttribute(k_x5, cudaFuncAttributeMaxDynamicSharedMemorySize, XS_TOTAL);

    k_zero<<<1, 32>>>();
    k_build<<<MT, DIN>>>(z, x2, mk);
    k_x5<<<dim3(24, 512), 256, XS_TOTAL>>>(W5);
    k_recur<<<NBLK, RTH, SMEM_DYN>>>(U5, W6, U6, bi5, br5, bi6, br6);
    k_dense<<<TT, 128>>>(Wd, bd, dmk, out);
}